// round 1
// baseline (speedup 1.0000x reference)
#include <cuda_runtime.h>
#include <math_constants.h>

// Problem constants (from reference): B=512, D=256, C=100000, m=4, lambda=1000
#define MAX_C 100000
#define MAX_B 512

// Scratch (allocation-free rule: __device__ globals)
__device__ float g_wlen_inv[MAX_C];
__device__ float g_xlen[MAX_B];
__device__ float g_xlen_inv[MAX_B];

// ---------------------------------------------------------------------------
// Row-norm kernels: one warp per row, D assumed multiple of 4 (D=256).
// ---------------------------------------------------------------------------
__global__ void wnorm_kernel(const float* __restrict__ W, int C, int D) {
    int row  = (blockIdx.x * blockDim.x + threadIdx.x) >> 5;
    int lane = threadIdx.x & 31;
    if (row >= C) return;
    const float* p = W + (size_t)row * D;
    float s = 0.f;
    for (int i = lane * 4; i < D; i += 128) {
        float4 v = *(const float4*)(p + i);
        s += v.x * v.x + v.y * v.y + v.z * v.z + v.w * v.w;
    }
    #pragma unroll
    for (int o = 16; o; o >>= 1) s += __shfl_xor_sync(0xffffffffu, s, o);
    if (lane == 0) g_wlen_inv[row] = 1.0f / sqrtf(s);
}

__global__ void xnorm_kernel(const float* __restrict__ X, int B, int D) {
    int row  = (blockIdx.x * blockDim.x + threadIdx.x) >> 5;
    int lane = threadIdx.x & 31;
    if (row >= B) return;
    const float* p = X + (size_t)row * D;
    float s = 0.f;
    for (int i = lane * 4; i < D; i += 128) {
        float4 v = *(const float4*)(p + i);
        s += v.x * v.x + v.y * v.y + v.z * v.z + v.w * v.w;
    }
    #pragma unroll
    for (int o = 16; o; o >>= 1) s += __shfl_xor_sync(0xffffffffu, s, o);
    if (lane == 0) {
        float l = sqrtf(s);
        g_xlen[row]     = l;
        g_xlen_inv[row] = 1.0f / l;
    }
}

// ---------------------------------------------------------------------------
// Fused GEMM + AngleSoftmax epilogue.
// Tile: 128x128, BK=8, 256 threads, 8x8 per-thread microtile,
// double-buffered smem, float4 global loads, +4 smem padding.
// ---------------------------------------------------------------------------
#define TM 128
#define TN 128
#define TK 8
#define PAD 4

__global__ __launch_bounds__(256, 2)
void angle_gemm_kernel(const float* __restrict__ X, const float* __restrict__ W,
                       const int* __restrict__ Y, float* __restrict__ out,
                       int B, int C, int D)
{
    __shared__ float As[2][TK][TM + PAD];
    __shared__ float Bs[2][TK][TN + PAD];

    const int tid = threadIdx.x;
    const int bm  = blockIdx.y * TM;
    const int bn  = blockIdx.x * TN;

    // Global load mapping: 256 threads, each loads one float4 of A and one of B
    const int lrow = tid >> 1;          // 0..127
    const int lcol = (tid & 1) * 4;     // 0 or 4

    const int arow = bm + lrow;
    const int brow = bn + lrow;                 // class index (may exceed C)
    const bool avalid = (arow < B);
    const bool bvalid = (brow < C);

    const float* aptr = X + (size_t)(avalid ? arow : 0) * D + lcol;
    const float* bptr = W + (size_t)(bvalid ? brow : 0) * D + lcol;

    const float4 fz = make_float4(0.f, 0.f, 0.f, 0.f);

    // Prologue: load k-block 0 into buffer 0
    float4 ra = avalid ? *(const float4*)aptr : fz;
    float4 rb = bvalid ? *(const float4*)bptr : fz;
    As[0][lcol + 0][lrow] = ra.x;
    As[0][lcol + 1][lrow] = ra.y;
    As[0][lcol + 2][lrow] = ra.z;
    As[0][lcol + 3][lrow] = ra.w;
    Bs[0][lcol + 0][lrow] = rb.x;
    Bs[0][lcol + 1][lrow] = rb.y;
    Bs[0][lcol + 2][lrow] = rb.z;
    Bs[0][lcol + 3][lrow] = rb.w;
    __syncthreads();

    float acc[8][8];
    #pragma unroll
    for (int i = 0; i < 8; i++)
        #pragma unroll
        for (int j = 0; j < 8; j++) acc[i][j] = 0.f;

    const int tx = tid & 15;   // column group
    const int ty = tid >> 4;   // row group

    int buf = 0;
    for (int k0 = 0; k0 < D; k0 += TK) {
        const int knext = k0 + TK;
        const bool hn = (knext < D);
        if (hn) {
            ra = avalid ? *(const float4*)(aptr + knext) : fz;
            rb = bvalid ? *(const float4*)(bptr + knext) : fz;
        }

        #pragma unroll
        for (int kk = 0; kk < TK; kk++) {
            float4 a0 = *(const float4*)&As[buf][kk][ty * 8];
            float4 a1 = *(const float4*)&As[buf][kk][ty * 8 + 4];
            float4 b0 = *(const float4*)&Bs[buf][kk][tx * 8];
            float4 b1 = *(const float4*)&Bs[buf][kk][tx * 8 + 4];
            float a[8] = {a0.x, a0.y, a0.z, a0.w, a1.x, a1.y, a1.z, a1.w};
            float b[8] = {b0.x, b0.y, b0.z, b0.w, b1.x, b1.y, b1.z, b1.w};
            #pragma unroll
            for (int i = 0; i < 8; i++)
                #pragma unroll
                for (int j = 0; j < 8; j++)
                    acc[i][j] = fmaf(a[i], b[j], acc[i][j]);
        }

        if (hn) {
            As[buf ^ 1][lcol + 0][lrow] = ra.x;
            As[buf ^ 1][lcol + 1][lrow] = ra.y;
            As[buf ^ 1][lcol + 2][lrow] = ra.z;
            As[buf ^ 1][lcol + 3][lrow] = ra.w;
            Bs[buf ^ 1][lcol + 0][lrow] = rb.x;
            Bs[buf ^ 1][lcol + 1][lrow] = rb.y;
            Bs[buf ^ 1][lcol + 2][lrow] = rb.z;
            Bs[buf ^ 1][lcol + 3][lrow] = rb.w;
            __syncthreads();
            buf ^= 1;
        }
    }

    // Epilogue: cos -> feat, margin at label columns
    const float inv_pi      = 1.0f / CUDART_PI_F;
    const float inv_1plamb  = 1.0f / 1001.0f;   // 1/(1+lambda), lambda=1000

    #pragma unroll
    for (int i = 0; i < 8; i++) {
        const int r = bm + ty * 8 + i;
        if (r >= B) continue;
        const float xl  = g_xlen[r];
        const float xli = g_xlen_inv[r];
        const int   lab = Y[r];
        const size_t base = (size_t)r * C;
        #pragma unroll
        for (int j = 0; j < 8; j++) {
            const int c = bn + tx * 8 + j;
            if (c >= C) continue;
            const float wli  = g_wlen_inv[c];
            float cosv = acc[i][j] * wli * xli;
            cosv = fminf(fmaxf(cosv, -1.0f), 1.0f);
            float feat = cosv * xl;
            if (c == lab) {
                const float c2   = cosv * cosv;
                const float cosm = 8.0f * c2 * c2 - 8.0f * c2 + 1.0f;
                const float kf   = floorf(4.0f * acosf(cosv) * inv_pi);
                const float sign = 1.0f - 2.0f * fmodf(kf, 2.0f);
                const float phi  = sign * cosm - 2.0f * kf;
                feat += (phi * xl - feat) * inv_1plamb;
            }
            out[base + c] = feat;
        }
    }
}

// ---------------------------------------------------------------------------
// Launch
// ---------------------------------------------------------------------------
extern "C" void kernel_launch(void* const* d_in, const int* in_sizes, int n_in,
                              void* d_out, int out_size)
{
    const float* x = (const float*)d_in[0];
    const float* w = (const float*)d_in[1];
    const int*   y = (const int*)d_in[2];
    float* out     = (float*)d_out;

    const int B = in_sizes[2];            // 512
    const int D = in_sizes[0] / B;        // 256
    const int C = in_sizes[1] / D;        // 100000

    // Row norms (8 warps / block)
    {
        int warps_per_block = 8;
        int blocks = (C + warps_per_block - 1) / warps_per_block;
        wnorm_kernel<<<blocks, warps_per_block * 32>>>(w, C, D);
        blocks = (B + warps_per_block - 1) / warps_per_block;
        xnorm_kernel<<<blocks, warps_per_block * 32>>>(x, B, D);
    }

    // Fused GEMM + margin epilogue
    dim3 grid((C + TN - 1) / TN, (B + TM - 1) / TM);
    angle_gemm_kernel<<<grid, 256>>>(x, w, y, out, B, C, D);
}

// round 3
// speedup vs baseline: 5.9404x; 5.9404x over previous
#include <cuda_runtime.h>
#include <cuda_fp16.h>
#include <math_constants.h>
#include <cstdint>

// Problem constants: B=512, D=256, C=100000, m=4, lambda=1000
#define MAX_C 100000
#define MAX_B 512
#define DD    256

// ---------------------------------------------------------------------------
// Device scratch (allocation-free rule: __device__ globals)
// ---------------------------------------------------------------------------
__device__ __half g_wh[(size_t)MAX_C * DD];   // fp16(normalized W)   51.2 MB
__device__ __half g_xh[(size_t)MAX_B * DD];   // fp16(normalized X)
__device__ float  g_xlen[MAX_B];

// ---------------------------------------------------------------------------
// Helpers
// ---------------------------------------------------------------------------
__device__ __forceinline__ uint32_t smem_u32(const void* p) {
    uint32_t a;
    asm("{ .reg .u64 t; cvta.to.shared.u64 t, %1; cvt.u32.u64 %0, t; }" : "=r"(a) : "l"(p));
    return a;
}
__device__ __forceinline__ void cp_async16(uint32_t dst, const void* src) {
    asm volatile("cp.async.cg.shared.global [%0], [%1], 16;" :: "r"(dst), "l"(src));
}
__device__ __forceinline__ void cp_commit() {
    asm volatile("cp.async.commit_group;" ::: "memory");
}
template <int N> __device__ __forceinline__ void cp_wait() {
    asm volatile("cp.async.wait_group %0;" :: "n"(N) : "memory");
}
__device__ __forceinline__ void ldsm_x4(uint32_t& r0, uint32_t& r1, uint32_t& r2, uint32_t& r3,
                                        uint32_t addr) {
    asm volatile("ldmatrix.sync.aligned.m8n8.x4.shared.b16 {%0,%1,%2,%3}, [%4];"
                 : "=r"(r0), "=r"(r1), "=r"(r2), "=r"(r3) : "r"(addr));
}
__device__ __forceinline__ void mma_16816(float& c0, float& c1, float& c2, float& c3,
                                          uint32_t a0, uint32_t a1, uint32_t a2, uint32_t a3,
                                          uint32_t b0, uint32_t b1) {
    asm volatile("mma.sync.aligned.m16n8k16.row.col.f32.f16.f16.f32 "
                 "{%0,%1,%2,%3}, {%4,%5,%6,%7}, {%8,%9}, {%0,%1,%2,%3};"
                 : "+f"(c0), "+f"(c1), "+f"(c2), "+f"(c3)
                 : "r"(a0), "r"(a1), "r"(a2), "r"(a3), "r"(b0), "r"(b1));
}

// ---------------------------------------------------------------------------
// Prep: normalize rows -> fp16. One warp per row, D = 256.
// ---------------------------------------------------------------------------
__global__ void wprep_kernel(const float* __restrict__ W, int C) {
    int row  = (blockIdx.x * blockDim.x + threadIdx.x) >> 5;
    int lane = threadIdx.x & 31;
    if (row >= C) return;
    const float* p = W + (size_t)row * DD;
    float4 v0 = *(const float4*)(p + lane * 4);
    float4 v1 = *(const float4*)(p + 128 + lane * 4);
    float s = v0.x*v0.x + v0.y*v0.y + v0.z*v0.z + v0.w*v0.w
            + v1.x*v1.x + v1.y*v1.y + v1.z*v1.z + v1.w*v1.w;
    #pragma unroll
    for (int o = 16; o; o >>= 1) s += __shfl_xor_sync(0xffffffffu, s, o);
    float inv = rsqrtf(s);
    __half2 h0 = __floats2half2_rn(v0.x * inv, v0.y * inv);
    __half2 h1 = __floats2half2_rn(v0.z * inv, v0.w * inv);
    __half2 h2 = __floats2half2_rn(v1.x * inv, v1.y * inv);
    __half2 h3 = __floats2half2_rn(v1.z * inv, v1.w * inv);
    size_t base = (size_t)row * DD;
    *(__half2*)(g_wh + base + lane * 4)           = h0;
    *(__half2*)(g_wh + base + lane * 4 + 2)       = h1;
    *(__half2*)(g_wh + base + 128 + lane * 4)     = h2;
    *(__half2*)(g_wh + base + 128 + lane * 4 + 2) = h3;
}

__global__ void xprep_kernel(const float* __restrict__ X, int B) {
    int row  = (blockIdx.x * blockDim.x + threadIdx.x) >> 5;
    int lane = threadIdx.x & 31;
    if (row >= B) return;
    const float* p = X + (size_t)row * DD;
    float4 v0 = *(const float4*)(p + lane * 4);
    float4 v1 = *(const float4*)(p + 128 + lane * 4);
    float s = v0.x*v0.x + v0.y*v0.y + v0.z*v0.z + v0.w*v0.w
            + v1.x*v1.x + v1.y*v1.y + v1.z*v1.z + v1.w*v1.w;
    #pragma unroll
    for (int o = 16; o; o >>= 1) s += __shfl_xor_sync(0xffffffffu, s, o);
    float len = sqrtf(s);
    float inv = 1.0f / len;
    if (lane == 0) g_xlen[row] = len;
    __half2 h0 = __floats2half2_rn(v0.x * inv, v0.y * inv);
    __half2 h1 = __floats2half2_rn(v0.z * inv, v0.w * inv);
    __half2 h2 = __floats2half2_rn(v1.x * inv, v1.y * inv);
    __half2 h3 = __floats2half2_rn(v1.z * inv, v1.w * inv);
    size_t base = (size_t)row * DD;
    *(__half2*)(g_xh + base + lane * 4)           = h0;
    *(__half2*)(g_xh + base + lane * 4 + 2)       = h1;
    *(__half2*)(g_xh + base + 128 + lane * 4)     = h2;
    *(__half2*)(g_xh + base + 128 + lane * 4 + 2) = h3;
}

// ---------------------------------------------------------------------------
// mma.sync GEMM + AngleSoftmax epilogue
// CTA 128x128, BK=64, 8 warps (2m x 4n), warp tile 64x32, 3-stage cp.async.
// ---------------------------------------------------------------------------
#define BM 128
#define BN 128
#define BK 64
#define NSTAGE 3
#define NCHUNK (DD / BK)                     // 4
#define STAGE_BYTES (BM * 128 + BN * 128)    // 32768 (A 16K + B 16K; 128B rows)
#define SMEM_TOTAL  (NSTAGE * STAGE_BYTES)   // 98304

// smem xor swizzle for 128-byte rows: blk' = blk ^ (row % 8)
__device__ __forceinline__ uint32_t sw_off(int row, int blk) {
    return (uint32_t)(row * 128 + ((blk ^ (row & 7)) * 16));
}

__global__ __launch_bounds__(256, 2)
void angle_mma_kernel(const int* __restrict__ Y, float* __restrict__ out, int C)
{
    extern __shared__ char smem[];
    const uint32_t sbase = smem_u32(smem);
    const int tid  = threadIdx.x;
    const int wid  = tid >> 5;
    const int lane = tid & 31;
    const int wm   = wid >> 2;     // 0..1 : warp m (64 rows)
    const int wn   = wid & 3;      // 0..3 : warp n (32 cols)

    const int bm = blockIdx.x * BM;
    const int bn = blockIdx.y * BN;

    // ---- load one k-chunk into a stage ----
    auto load_chunk = [&](int stage, int kc) {
        const uint32_t abase = sbase + stage * STAGE_BYTES;
        const uint32_t bbase = abase + BM * 128;
        #pragma unroll
        for (int i = 0; i < 8; i++) {
            int t = tid + i * 256;           // 0..2047
            int row = (t >> 3) & 127;
            int blk = t & 7;
            if (t < 1024) {
                cp_async16(abase + sw_off(row, blk),
                           g_xh + (size_t)(bm + row) * DD + kc + blk * 8);
            } else {
                int rg = bn + row; if (rg >= C) rg = C - 1;
                cp_async16(bbase + sw_off(row, blk),
                           g_wh + (size_t)rg * DD + kc + blk * 8);
            }
        }
        cp_commit();
    };

    // ---- prologue: chunks 0,1 ----
    load_chunk(0, 0);
    load_chunk(1, BK);

    float c[4][4][4];
    #pragma unroll
    for (int mt = 0; mt < 4; mt++)
        #pragma unroll
        for (int nt = 0; nt < 4; nt++)
            #pragma unroll
            for (int q = 0; q < 4; q++) c[mt][nt][q] = 0.f;

    // per-lane ldmatrix row components (fixed across chunks)
    const int a_hi = lane >> 4;                       // k half
    int a_row[4], b_row[2];
    #pragma unroll
    for (int mt = 0; mt < 4; mt++) a_row[mt] = wm * 64 + mt * 16 + (lane & 15);
    #pragma unroll
    for (int bt = 0; bt < 2; bt++) b_row[bt] = wn * 32 + bt * 16 + ((lane >> 3) & 1) * 8 + (lane & 7);

    // ---- main loop ----
    #pragma unroll
    for (int ck = 0; ck < NCHUNK; ck++) {
        if (ck == NCHUNK - 1) cp_wait<0>(); else cp_wait<1>();
        __syncthreads();
        if (ck + 2 < NCHUNK) load_chunk((ck + 2) % NSTAGE, (ck + 2) * BK);

        const uint32_t abase = sbase + (ck % NSTAGE) * STAGE_BYTES;
        const uint32_t bbase = abase + BM * 128;

        #pragma unroll
        for (int ks = 0; ks < 4; ks++) {
            uint32_t a[4][4], b[2][4];
            #pragma unroll
            for (int mt = 0; mt < 4; mt++)
                ldsm_x4(a[mt][0], a[mt][1], a[mt][2], a[mt][3],
                        abase + sw_off(a_row[mt], ks * 2 + a_hi));
            #pragma unroll
            for (int bt = 0; bt < 2; bt++)
                ldsm_x4(b[bt][0], b[bt][1], b[bt][2], b[bt][3],
                        bbase + sw_off(b_row[bt], ks * 2 + a_hi));
            #pragma unroll
            for (int mt = 0; mt < 4; mt++) {
                #pragma unroll
                for (int nt = 0; nt < 4; nt++) {
                    const int bt = nt >> 1, sub = nt & 1;
                    mma_16816(c[mt][nt][0], c[mt][nt][1], c[mt][nt][2], c[mt][nt][3],
                              a[mt][0], a[mt][1], a[mt][2], a[mt][3],
                              b[bt][sub], b[bt][2 + sub]);
                }
            }
        }
    }

    // ---- epilogue: cos -> feat (+ margin at label) ----
    const float inv_pi     = 1.0f / CUDART_PI_F;
    const float inv_1plamb = 1.0f / 1001.0f;

    #pragma unroll
    for (int mt = 0; mt < 4; mt++) {
        const int r0 = bm + wm * 64 + mt * 16 + (lane >> 2);
        const int r1 = r0 + 8;
        const float xl0 = g_xlen[r0], xl1 = g_xlen[r1];
        const int  lab0 = Y[r0],      lab1 = Y[r1];
        #pragma unroll
        for (int nt = 0; nt < 4; nt++) {
            const int col = bn + wn * 32 + nt * 8 + (lane & 3) * 2;
            if (col >= C) continue;          // col even, C even -> col+1 < C too
            #pragma unroll
            for (int half = 0; half < 2; half++) {
                const int   rr  = half ? r1 : r0;
                const float xl  = half ? xl1 : xl0;
                const int   lab = half ? lab1 : lab0;
                float v0 = c[mt][nt][half * 2 + 0];
                float v1 = c[mt][nt][half * 2 + 1];
                v0 = fminf(fmaxf(v0, -1.0f), 1.0f);
                v1 = fminf(fmaxf(v1, -1.0f), 1.0f);
                float f0 = v0 * xl, f1 = v1 * xl;
                if (col == lab || col + 1 == lab) {
                    const bool second = (col + 1 == lab);
                    float cv = second ? v1 : v0;
                    float c2   = cv * cv;
                    float cosm = 8.0f * c2 * c2 - 8.0f * c2 + 1.0f;
                    float kf   = floorf(4.0f * acosf(cv) * inv_pi);
                    float sign = 1.0f - 2.0f * fmodf(kf, 2.0f);
                    float phi  = sign * cosm - 2.0f * kf;
                    float fm   = (second ? f1 : f0) ;
                    fm += (phi * xl - fm) * inv_1plamb;
                    if (second) f1 = fm; else f0 = fm;
                }
                *(float2*)(out + (size_t)rr * C + col) = make_float2(f0, f1);
            }
        }
    }
}

// ---------------------------------------------------------------------------
// Launch
// ---------------------------------------------------------------------------
extern "C" void kernel_launch(void* const* d_in, const int* in_sizes, int n_in,
                              void* d_out, int out_size)
{
    const float* x = (const float*)d_in[0];
    const float* w = (const float*)d_in[1];
    const int*   y = (const int*)d_in[2];
    float* out     = (float*)d_out;

    const int B = in_sizes[2];            // 512
    const int D = in_sizes[0] / B;        // 256
    const int C = in_sizes[1] / D;        // 100000

    static bool attr_set = false;
    if (!attr_set) {
        cudaFuncSetAttribute(angle_mma_kernel,
                             cudaFuncAttributeMaxDynamicSharedMemorySize, SMEM_TOTAL);
        attr_set = true;
    }

    {
        int wpb = 8;
        wprep_kernel<<<(C + wpb - 1) / wpb, wpb * 32>>>(w, C);
        xprep_kernel<<<(B + wpb - 1) / wpb, wpb * 32>>>(x, B);
    }

    // grid.x = m tiles (fastest -> adjacent CTAs share the same W n-stripe in L2)
    dim3 grid(B / BM, (C + BN - 1) / BN);
    angle_mma_kernel<<<grid, 256, SMEM_TOTAL>>>(y, out, C);
}